// round 1
// baseline (speedup 1.0000x reference)
#include <cuda_runtime.h>
#include <cstdint>

#define G 32           // groups
#define CG 2           // channels per group (C=64)
#define MAXB 1024      // max supported batch size for scratch sizing
#define EPSF 1e-5f

// Scratch (device globals: allocation-free per harness rules)
__device__ float  g_s1[MAXB * G];
__device__ float  g_s2[MAXB * G];
__device__ float  g_cnt[MAXB];
__device__ float4 g_tab[MAXB * G];   // (A0, A1, D0, D1) per (b, g)

// ---------------------------------------------------------------------------
// Zero scratch (B read on device; grid covers MAXB*G worst case)
// ---------------------------------------------------------------------------
__global__ void zero_kernel(const int* __restrict__ Bp) {
    int B = *Bp;
    if (B > MAXB) B = MAXB;
    int i = blockIdx.x * blockDim.x + threadIdx.x;
    if (i < B * G) { g_s1[i] = 0.0f; g_s2[i] = 0.0f; }
    if (i < B)     { g_cnt[i] = 0.0f; }
}

// ---------------------------------------------------------------------------
// Count points per batch. Fast path (B<=8): ballot/popc histogram in regs.
// ---------------------------------------------------------------------------
__global__ void __launch_bounds__(256) count_kernel(const int* __restrict__ bidx,
                                                    int N, const int* __restrict__ Bp) {
    int B = *Bp;
    int lane = threadIdx.x & 31;
    int warp = (blockIdx.x * blockDim.x + threadIdx.x) >> 5;
    int nwarps = (gridDim.x * blockDim.x) >> 5;

    if (B <= 8) {
        float c[8];
#pragma unroll
        for (int bb = 0; bb < 8; bb++) c[bb] = 0.0f;
        for (int base = warp * 32; base < N; base += nwarps * 32) {
            int i = base + lane;
            int b = (i < N) ? __ldg(bidx + i) : -1;
#pragma unroll
            for (int bb = 0; bb < 8; bb++) {
                unsigned m = __ballot_sync(0xFFFFFFFFu, b == bb);
                if (lane == 0) c[bb] += (float)__popc(m);
            }
        }
        if (lane == 0) {
#pragma unroll
            for (int bb = 0; bb < 8; bb++)
                if (c[bb] != 0.0f) atomicAdd(&g_cnt[bb], c[bb]);
        }
    } else {
        // generic fallback: per-element global atomic (rare path)
        int i0 = blockIdx.x * blockDim.x + threadIdx.x;
        int stride = gridDim.x * blockDim.x;
        for (int i = i0; i < N; i += stride) {
            int b = __ldg(bidx + i);
            if (b >= 0 && b < MAXB) atomicAdd(&g_cnt[b], 1.0f);
        }
    }
}

// ---------------------------------------------------------------------------
// Pass 1 (fast, B<=8): register-predicated accumulation.
// Warp-per-point; lane L owns group L (channels 2L, 2L+1).
// ---------------------------------------------------------------------------
__global__ void __launch_bounds__(256) reduce8_kernel(const float* __restrict__ feat,
                                                      const int* __restrict__ bidx,
                                                      int N, const int* __restrict__ Bp) {
    int B = *Bp;
    if (B > 8) return;

    int lane = threadIdx.x & 31;
    int warp = (blockIdx.x * blockDim.x + threadIdx.x) >> 5;
    int nwarps = (gridDim.x * blockDim.x) >> 5;

    float s1[8], s2[8];
#pragma unroll
    for (int bb = 0; bb < 8; bb++) { s1[bb] = 0.0f; s2[bb] = 0.0f; }

    int stride = nwarps;
    for (int p = warp; p < N; p += 4 * stride) {
#pragma unroll
        for (int j = 0; j < 4; j++) {
            int q = p + j * stride;
            if (q < N) {
                int b = __ldg(bidx + q);
                float2 x = __ldg(reinterpret_cast<const float2*>(
                                 feat + (size_t)q * 64 + 2 * lane));
                float v  = x.x + x.y;
                float v2 = fmaf(x.x, x.x, x.y * x.y);
#pragma unroll
                for (int bb = 0; bb < 8; bb++) {
                    if (bb == b) { s1[bb] += v; s2[bb] += v2; }
                }
            }
        }
    }

    // block-level reduction in shared, then 512 global atomics per block
    __shared__ float sh1[8 * G];
    __shared__ float sh2[8 * G];
    for (int i = threadIdx.x; i < 8 * G; i += blockDim.x) { sh1[i] = 0.0f; sh2[i] = 0.0f; }
    __syncthreads();
#pragma unroll
    for (int bb = 0; bb < 8; bb++) {
        atomicAdd(&sh1[bb * G + lane], s1[bb]);
        atomicAdd(&sh2[bb * G + lane], s2[bb]);
    }
    __syncthreads();
    int i = threadIdx.x;            // exactly 256 = 8*G entries
    if (sh1[i] != 0.0f || sh2[i] != 0.0f) {
        atomicAdd(&g_s1[i], sh1[i]);
        atomicAdd(&g_s2[i], sh2[i]);
    }
}

// ---------------------------------------------------------------------------
// Pass 1 (generic, B>8): per-point global atomics. Correct but slow; only
// taken if batch_size > 8 (never in this dataset). Early-exits otherwise.
// ---------------------------------------------------------------------------
__global__ void __launch_bounds__(256) reduce_gen_kernel(const float* __restrict__ feat,
                                                         const int* __restrict__ bidx,
                                                         int N, const int* __restrict__ Bp) {
    int B = *Bp;
    if (B <= 8) return;
    int lane = threadIdx.x & 31;
    int warp = (blockIdx.x * blockDim.x + threadIdx.x) >> 5;
    int nwarps = (gridDim.x * blockDim.x) >> 5;
    for (int p = warp; p < N; p += nwarps) {
        int b = __ldg(bidx + p);
        if (b < 0 || b >= MAXB) continue;
        float2 x = __ldg(reinterpret_cast<const float2*>(feat + (size_t)p * 64 + 2 * lane));
        atomicAdd(&g_s1[b * G + lane], x.x + x.y);
        atomicAdd(&g_s2[b * G + lane], fmaf(x.x, x.x, x.y * x.y));
    }
}

// ---------------------------------------------------------------------------
// Finalize: mean/var/inv -> fused affine table (A0,A1,D0,D1) per (b,g)
//   out = x*inv*w + (bias - mean*inv*w)
// ---------------------------------------------------------------------------
__global__ void finalize_kernel(const float* __restrict__ w,
                                const float* __restrict__ bias,
                                const int* __restrict__ Bp) {
    int B = *Bp;
    if (B > MAXB) B = MAXB;
    int i = blockIdx.x * blockDim.x + threadIdx.x;
    if (i >= B * G) return;
    int b = i / G;
    int g = i - b * G;
    float cnt = fmaxf(g_cnt[b] * (float)CG, 1.0f);
    float mean = g_s1[i] / cnt;
    float var  = g_s2[i] / cnt - mean * mean;
    float inv  = rsqrtf(var + EPSF);
    float w0 = w[2 * g], w1 = w[2 * g + 1];
    float b0 = bias[2 * g], b1 = bias[2 * g + 1];
    float A0 = inv * w0, A1 = inv * w1;
    g_tab[i] = make_float4(A0, A1, b0 - mean * A0, b1 - mean * A1);
}

// ---------------------------------------------------------------------------
// Pass 3: normalize. Warp-per-point, lane L handles channels 2L,2L+1.
// ---------------------------------------------------------------------------
__global__ void __launch_bounds__(256) normalize_kernel(const float* __restrict__ feat,
                                                        const int* __restrict__ bidx,
                                                        float* __restrict__ out, int N) {
    int lane = threadIdx.x & 31;
    int warp = (blockIdx.x * blockDim.x + threadIdx.x) >> 5;
    int nwarps = (gridDim.x * blockDim.x) >> 5;

    int stride = nwarps;
    for (int p = warp; p < N; p += 4 * stride) {
#pragma unroll
        for (int j = 0; j < 4; j++) {
            int q = p + j * stride;
            if (q < N) {
                int b = __ldg(bidx + q);
                float4 t = __ldg(&g_tab[b * G + lane]);
                size_t off = (size_t)q * 64 + 2 * lane;
                float2 x = __ldg(reinterpret_cast<const float2*>(feat + off));
                float2 y;
                y.x = fmaf(x.x, t.x, t.z);
                y.y = fmaf(x.y, t.y, t.w);
                *reinterpret_cast<float2*>(out + off) = y;
            }
        }
    }
}

// ---------------------------------------------------------------------------
// kernel_launch
// inputs: 0=features [N*64] f32, 1=weight [64] f32, 2=bias [64] f32,
//         3=batch_idx [N] i32, 4=batch_size [1] i32 (device scalar)
// ---------------------------------------------------------------------------
extern "C" void kernel_launch(void* const* d_in, const int* in_sizes, int n_in,
                              void* d_out, int out_size) {
    const float* feat = (const float*)d_in[0];
    const float* w    = (const float*)d_in[1];
    const float* bias = (const float*)d_in[2];
    const int*   bidx = (const int*)d_in[3];
    const int*   Bp   = (const int*)d_in[4];
    float* out = (float*)d_out;

    int C = in_sizes[1];                 // expected 64
    int N = in_sizes[0] / (C > 0 ? C : 64);

    int threads = 256;
    int warps_needed = (N + 0) ;         // 1 warp per point min granularity
    int big_blocks = (warps_needed + 7) / 8;
    if (big_blocks > 1184) big_blocks = 1184;   // 148 SMs * 8 blocks
    if (big_blocks < 1) big_blocks = 1;

    int small_blocks = (MAXB * G + threads - 1) / threads;

    zero_kernel<<<small_blocks, threads>>>(Bp);
    count_kernel<<<592, threads>>>(bidx, N, Bp);
    reduce8_kernel<<<big_blocks, threads>>>(feat, bidx, N, Bp);
    reduce_gen_kernel<<<big_blocks, threads>>>(feat, bidx, N, Bp);
    finalize_kernel<<<small_blocks, threads>>>(w, bias, Bp);
    normalize_kernel<<<big_blocks, threads>>>(feat, bidx, out, N);
}

// round 2
// speedup vs baseline: 1.1376x; 1.1376x over previous
#include <cuda_runtime.h>
#include <cstdint>

#define G 32           // groups
#define CG 2           // channels per group (C=64)
#define MAXB 1024      // max supported batch size for scratch sizing
#define EPSF 1e-5f

// Scratch (device globals: allocation-free per harness rules).
// Zero-initialized at module load; finalize_kernel self-resets them after
// consuming, so every graph replay sees zeroed accumulators.
__device__ float  g_s1[MAXB * G];
__device__ float  g_s2[MAXB * G];
__device__ float  g_cnt[MAXB];
__device__ float2 g_mi[MAXB * G];    // (mean, inv) per (b, g)

// ---------------------------------------------------------------------------
// Kernel 1: stats. Warp-per-point, lane L owns group L (channels 2L,2L+1).
// Fast path (B<=8): register-predicated bin accumulation incl. counts.
// Generic path (B>8): per-point global atomics (never taken for this dataset).
// ---------------------------------------------------------------------------
__global__ void __launch_bounds__(256) stats_kernel(const float* __restrict__ feat,
                                                    const int* __restrict__ bidx,
                                                    int N, const int* __restrict__ Bp) {
    const int B = *Bp;
    const int lane  = threadIdx.x & 31;
    const int gwarp = (blockIdx.x * blockDim.x + threadIdx.x) >> 5;
    const int nwarps = (gridDim.x * blockDim.x) >> 5;

    if (B <= 8) {
        float s1[8], s2[8], c[8];
#pragma unroll
        for (int bb = 0; bb < 8; bb++) { s1[bb] = 0.0f; s2[bb] = 0.0f; c[bb] = 0.0f; }

        // Contiguous 4-point run per warp-iteration (1KB contiguous / warp)
        int base = gwarp * 4;
        const int stride = nwarps * 4;
        for (; base + 3 < N; base += stride) {
#pragma unroll
            for (int j = 0; j < 4; j++) {
                const int q = base + j;
                const int b = __ldg(bidx + q);
                const float2 x = __ldg(reinterpret_cast<const float2*>(
                                       feat + (size_t)q * 64) + lane);
                const float v  = x.x + x.y;
                const float v2 = fmaf(x.x, x.x, x.y * x.y);
#pragma unroll
                for (int bb = 0; bb < 8; bb++) {
                    if (b == bb) { s1[bb] += v; s2[bb] += v2; c[bb] += 1.0f; }
                }
            }
        }
        // tail
        for (; base < N; base++) {
            const int b = __ldg(bidx + base);
            const float2 x = __ldg(reinterpret_cast<const float2*>(
                                   feat + (size_t)base * 64) + lane);
            const float v  = x.x + x.y;
            const float v2 = fmaf(x.x, x.x, x.y * x.y);
#pragma unroll
            for (int bb = 0; bb < 8; bb++) {
                if (b == bb) { s1[bb] += v; s2[bb] += v2; c[bb] += 1.0f; }
            }
        }

        // Block-level reduction in shared, then <=520 global atomics per block
        __shared__ float sh1[8 * G];
        __shared__ float sh2[8 * G];
        __shared__ float shc[8];
        for (int i = threadIdx.x; i < 8 * G; i += blockDim.x) { sh1[i] = 0.0f; sh2[i] = 0.0f; }
        if (threadIdx.x < 8) shc[threadIdx.x] = 0.0f;
        __syncthreads();
#pragma unroll
        for (int bb = 0; bb < 8; bb++) {
            atomicAdd(&sh1[bb * G + lane], s1[bb]);
            atomicAdd(&sh2[bb * G + lane], s2[bb]);
            if (lane == 0 && c[bb] != 0.0f) atomicAdd(&shc[bb], c[bb]);
        }
        __syncthreads();
        const int i = threadIdx.x;            // exactly 256 = 8*G entries
        if (sh1[i] != 0.0f || sh2[i] != 0.0f) {
            atomicAdd(&g_s1[i], sh1[i]);
            atomicAdd(&g_s2[i], sh2[i]);
        }
        if (i < 8 && shc[i] != 0.0f) atomicAdd(&g_cnt[i], shc[i]);
    } else {
        // Generic fallback: per-point global atomics (rare path)
        for (int p = gwarp; p < N; p += nwarps) {
            const int b = __ldg(bidx + p);
            if (b < 0 || b >= MAXB) continue;
            const float2 x = __ldg(reinterpret_cast<const float2*>(
                                   feat + (size_t)p * 64) + lane);
            atomicAdd(&g_s1[b * G + lane], x.x + x.y);
            atomicAdd(&g_s2[b * G + lane], fmaf(x.x, x.x, x.y * x.y));
            if (lane == 0) atomicAdd(&g_cnt[b], 1.0f);
        }
    }
}

// ---------------------------------------------------------------------------
// Kernel 2: finalize. mean/var/inv -> (mean, inv) table. Self-resets the
// accumulators so the next graph replay starts from zero.
// ---------------------------------------------------------------------------
__global__ void __launch_bounds__(256) finalize_kernel(const int* __restrict__ Bp) {
    int B = *Bp;
    if (B > MAXB) B = MAXB;
    const int i = blockIdx.x * blockDim.x + threadIdx.x;
    const bool active = (i < B * G);
    if (active) {
        const int b = i >> 5;
        const float cnt  = fmaxf(g_cnt[b] * (float)CG, 1.0f);
        const float mean = g_s1[i] / cnt;
        const float var  = g_s2[i] / cnt - mean * mean;
        const float inv  = rsqrtf(var + EPSF);
        g_mi[i] = make_float2(mean, inv);
        g_s1[i] = 0.0f;
        g_s2[i] = 0.0f;
    }
    __syncthreads();  // all readers of g_cnt[b] are in this block (32 | 256)
    if (active && (i & 31) == 0) g_cnt[i >> 5] = 0.0f;
}

// ---------------------------------------------------------------------------
// Kernel 3: normalize. Warp-per-point; per-lane weight/bias in registers,
// per-point table load is only 8B/lane (mean, inv).
//   out = (x - mean) * inv * w + bias
// ---------------------------------------------------------------------------
__global__ void __launch_bounds__(256) normalize_kernel(const float* __restrict__ feat,
                                                        const int* __restrict__ bidx,
                                                        const float* __restrict__ w,
                                                        const float* __restrict__ bias,
                                                        float* __restrict__ out, int N) {
    const int lane  = threadIdx.x & 31;
    const int gwarp = (blockIdx.x * blockDim.x + threadIdx.x) >> 5;
    const int nwarps = (gridDim.x * blockDim.x) >> 5;

    // Per-lane channel constants (2 channels per lane), loaded once.
    const float2 wv = __ldg(reinterpret_cast<const float2*>(w) + lane);
    const float2 bv = __ldg(reinterpret_cast<const float2*>(bias) + lane);

    int base = gwarp * 4;
    const int stride = nwarps * 4;
    for (; base + 3 < N; base += stride) {
#pragma unroll
        for (int j = 0; j < 4; j++) {
            const int q = base + j;
            const int b = __ldg(bidx + q);
            const float2 mi = __ldg(&g_mi[b * G + lane]);
            const size_t off = (size_t)q * 64 + 2 * lane;
            const float2 x = __ldg(reinterpret_cast<const float2*>(feat + off));
            const float iw0 = mi.y * wv.x;
            const float iw1 = mi.y * wv.y;
            float2 y;
            y.x = fmaf(x.x - mi.x, iw0, bv.x);
            y.y = fmaf(x.y - mi.x, iw1, bv.y);
            *reinterpret_cast<float2*>(out + off) = y;
        }
    }
    for (; base < N; base++) {
        const int b = __ldg(bidx + base);
        const float2 mi = __ldg(&g_mi[b * G + lane]);
        const size_t off = (size_t)base * 64 + 2 * lane;
        const float2 x = __ldg(reinterpret_cast<const float2*>(feat + off));
        const float iw0 = mi.y * wv.x;
        const float iw1 = mi.y * wv.y;
        float2 y;
        y.x = fmaf(x.x - mi.x, iw0, bv.x);
        y.y = fmaf(x.y - mi.x, iw1, bv.y);
        *reinterpret_cast<float2*>(out + off) = y;
    }
}

// ---------------------------------------------------------------------------
// kernel_launch
// inputs: 0=features [N*64] f32, 1=weight [64] f32, 2=bias [64] f32,
//         3=batch_idx [N] i32, 4=batch_size [1] i32 (device scalar)
// ---------------------------------------------------------------------------
extern "C" void kernel_launch(void* const* d_in, const int* in_sizes, int n_in,
                              void* d_out, int out_size) {
    const float* feat = (const float*)d_in[0];
    const float* w    = (const float*)d_in[1];
    const float* bias = (const float*)d_in[2];
    const int*   bidx = (const int*)d_in[3];
    const int*   Bp   = (const int*)d_in[4];
    float* out = (float*)d_out;

    const int N = in_sizes[3];           // batch_idx element count == N points

    const int threads = 256;
    int big_blocks = (N + 31) / 32;      // 8 warps/block, >=1 pt/warp
    if (big_blocks > 1184) big_blocks = 1184;   // 148 SMs * 8 blocks
    if (big_blocks < 1) big_blocks = 1;

    const int small_blocks = (MAXB * G + threads - 1) / threads;

    stats_kernel<<<big_blocks, threads>>>(feat, bidx, N, Bp);
    finalize_kernel<<<small_blocks, threads>>>(Bp);
    normalize_kernel<<<big_blocks, threads>>>(feat, bidx, w, bias, out, N);
}

// round 3
// speedup vs baseline: 1.6221x; 1.4260x over previous
#include <cuda_runtime.h>
#include <cstdint>

#define G 32           // groups
#define CG 2           // channels per group (C=64)
#define MAXB 1024      // max supported batch size for scratch sizing
#define EPSF 1e-5f
#define U 8            // points per warp-iteration in stats

// Scratch (device globals: allocation-free per harness rules).
// Zero-initialized at load; finalize self-resets after consuming, so every
// graph replay sees zeroed accumulators.
__device__ float  g_s1[MAXB * G];
__device__ float  g_s2[MAXB * G];
__device__ float  g_cnt[MAXB];
__device__ float2 g_mi[MAXB * G];    // (mean, inv) per (b, g)

// ---------------------------------------------------------------------------
// Kernel 1: stats. Warp-per-point, lane L owns group L (channels 2L,2L+1).
// Fast path (B<=8): batch 8 LDG.64 up front (MLP=8), then register-predicated
// bin accumulation. Count via the lane==b trick (1 reg, 1 FADD/point).
// ---------------------------------------------------------------------------
__global__ void __launch_bounds__(256, 5) stats_kernel(const float* __restrict__ feat,
                                                       const int* __restrict__ bidx,
                                                       int N, const int* __restrict__ Bp) {
    const int B = *Bp;
    const int lane   = threadIdx.x & 31;
    const int gwarp  = (blockIdx.x * blockDim.x + threadIdx.x) >> 5;
    const int nwarps = (gridDim.x * blockDim.x) >> 5;

    if (B <= 8) {
        float s1[8], s2[8];
#pragma unroll
        for (int bb = 0; bb < 8; bb++) { s1[bb] = 0.0f; s2[bb] = 0.0f; }
        float cnt = 0.0f;   // lane L accumulates count of bin L (L<8)

        int base = gwarp * U;
        const int stride = nwarps * U;
        for (; base + (U - 1) < N; base += stride) {
            // ---- phase 1: batch all loads (front-batched LDGs -> high MLP)
            const int myb = (lane < U) ? __ldg(bidx + base + lane) : 0;
            float2 xb[U];
#pragma unroll
            for (int j = 0; j < U; j++)
                xb[j] = __ldg(reinterpret_cast<const float2*>(
                              feat + (size_t)(base + j) * 64) + lane);
            // ---- phase 2: bin
#pragma unroll
            for (int j = 0; j < U; j++) {
                const int b = __shfl_sync(0xFFFFFFFFu, myb, j);
                const float v  = xb[j].x + xb[j].y;
                const float v2 = fmaf(xb[j].x, xb[j].x, xb[j].y * xb[j].y);
#pragma unroll
                for (int bb = 0; bb < 8; bb++) {
                    if (b == bb) { s1[bb] += v; s2[bb] += v2; }
                }
                if (lane == b) cnt += 1.0f;
            }
        }
        // tail
        for (; base < N; base++) {
            const int b = __ldg(bidx + base);
            const float2 x = __ldg(reinterpret_cast<const float2*>(
                                   feat + (size_t)base * 64) + lane);
            const float v  = x.x + x.y;
            const float v2 = fmaf(x.x, x.x, x.y * x.y);
#pragma unroll
            for (int bb = 0; bb < 8; bb++) {
                if (b == bb) { s1[bb] += v; s2[bb] += v2; }
            }
            if (lane == b) cnt += 1.0f;
        }

        // Block-level reduction in shared, then <=520 global atomics per block
        __shared__ float sh1[8 * G];
        __shared__ float sh2[8 * G];
        __shared__ float shc[8];
        for (int i = threadIdx.x; i < 8 * G; i += blockDim.x) { sh1[i] = 0.0f; sh2[i] = 0.0f; }
        if (threadIdx.x < 8) shc[threadIdx.x] = 0.0f;
        __syncthreads();
#pragma unroll
        for (int bb = 0; bb < 8; bb++) {
            atomicAdd(&sh1[bb * G + lane], s1[bb]);
            atomicAdd(&sh2[bb * G + lane], s2[bb]);
        }
        if (lane < 8 && cnt != 0.0f) atomicAdd(&shc[lane], cnt);
        __syncthreads();
        const int i = threadIdx.x;            // exactly 256 = 8*G entries
        if (sh1[i] != 0.0f || sh2[i] != 0.0f) {
            atomicAdd(&g_s1[i], sh1[i]);
            atomicAdd(&g_s2[i], sh2[i]);
        }
        if (i < 8 && shc[i] != 0.0f) atomicAdd(&g_cnt[i], shc[i]);
    } else {
        // Generic fallback: per-point global atomics (rare path)
        for (int p = gwarp; p < N; p += nwarps) {
            const int b = __ldg(bidx + p);
            if (b < 0 || b >= MAXB) continue;
            const float2 x = __ldg(reinterpret_cast<const float2*>(
                                   feat + (size_t)p * 64) + lane);
            atomicAdd(&g_s1[b * G + lane], x.x + x.y);
            atomicAdd(&g_s2[b * G + lane], fmaf(x.x, x.x, x.y * x.y));
            if (lane == 0) atomicAdd(&g_cnt[b], 1.0f);
        }
    }
}

// ---------------------------------------------------------------------------
// Kernel 2: finalize. mean/var/inv -> (mean, inv) table. Self-resets the
// accumulators so the next graph replay starts from zero.
// ---------------------------------------------------------------------------
__global__ void __launch_bounds__(256) finalize_kernel(const int* __restrict__ Bp) {
    int B = *Bp;
    if (B > MAXB) B = MAXB;
    const int i = blockIdx.x * blockDim.x + threadIdx.x;
    const bool active = (i < B * G);
    if (active) {
        const int b = i >> 5;
        const float cnt  = fmaxf(g_cnt[b] * (float)CG, 1.0f);
        const float mean = g_s1[i] / cnt;
        const float var  = g_s2[i] / cnt - mean * mean;
        const float inv  = rsqrtf(var + EPSF);
        g_mi[i] = make_float2(mean, inv);
        g_s1[i] = 0.0f;
        g_s2[i] = 0.0f;
    }
    __syncthreads();  // all readers of g_cnt[b] are in this block (32 | 256)
    if (active && (i & 31) == 0) g_cnt[i >> 5] = 0.0f;
}

// ---------------------------------------------------------------------------
// Kernel 3: normalize. Warp-per-point; per-lane weight/bias in registers,
// per-point table load is 8B/lane (mean, inv).
//   out = (x - mean) * inv * w + bias
// ---------------------------------------------------------------------------
__global__ void __launch_bounds__(256) normalize_kernel(const float* __restrict__ feat,
                                                        const int* __restrict__ bidx,
                                                        const float* __restrict__ w,
                                                        const float* __restrict__ bias,
                                                        float* __restrict__ out, int N) {
    const int lane   = threadIdx.x & 31;
    const int gwarp  = (blockIdx.x * blockDim.x + threadIdx.x) >> 5;
    const int nwarps = (gridDim.x * blockDim.x) >> 5;

    // Per-lane channel constants (2 channels per lane), loaded once.
    const float2 wv = __ldg(reinterpret_cast<const float2*>(w) + lane);
    const float2 bv = __ldg(reinterpret_cast<const float2*>(bias) + lane);

    int base = gwarp * 4;
    const int stride = nwarps * 4;
    for (; base + 3 < N; base += stride) {
#pragma unroll
        for (int j = 0; j < 4; j++) {
            const int q = base + j;
            const int b = __ldg(bidx + q);
            const float2 mi = __ldg(&g_mi[b * G + lane]);
            const size_t off = (size_t)q * 64 + 2 * lane;
            const float2 x = __ldg(reinterpret_cast<const float2*>(feat + off));
            const float iw0 = mi.y * wv.x;
            const float iw1 = mi.y * wv.y;
            float2 y;
            y.x = fmaf(x.x - mi.x, iw0, bv.x);
            y.y = fmaf(x.y - mi.x, iw1, bv.y);
            *reinterpret_cast<float2*>(out + off) = y;
        }
    }
    for (; base < N; base++) {
        const int b = __ldg(bidx + base);
        const float2 mi = __ldg(&g_mi[b * G + lane]);
        const size_t off = (size_t)base * 64 + 2 * lane;
        const float2 x = __ldg(reinterpret_cast<const float2*>(feat + off));
        const float iw0 = mi.y * wv.x;
        const float iw1 = mi.y * wv.y;
        float2 y;
        y.x = fmaf(x.x - mi.x, iw0, bv.x);
        y.y = fmaf(x.y - mi.x, iw1, bv.y);
        *reinterpret_cast<float2*>(out + off) = y;
    }
}

// ---------------------------------------------------------------------------
// kernel_launch
// inputs: 0=features [N*64] f32, 1=weight [64] f32, 2=bias [64] f32,
//         3=batch_idx [N] i32, 4=batch_size [1] i32 (device scalar)
// ---------------------------------------------------------------------------
extern "C" void kernel_launch(void* const* d_in, const int* in_sizes, int n_in,
                              void* d_out, int out_size) {
    const float* feat = (const float*)d_in[0];
    const float* w    = (const float*)d_in[1];
    const float* bias = (const float*)d_in[2];
    const int*   bidx = (const int*)d_in[3];
    const int*   Bp   = (const int*)d_in[4];
    float* out = (float*)d_out;

    const int N = in_sizes[3];           // batch_idx element count == N points

    const int threads = 256;
    int big_blocks = (N + 31) / 32;
    if (big_blocks > 1184) big_blocks = 1184;   // 148 SMs * 8 blocks
    if (big_blocks < 1) big_blocks = 1;

    const int small_blocks = (MAXB * G + threads - 1) / threads;

    stats_kernel<<<big_blocks, threads>>>(feat, bidx, N, Bp);
    finalize_kernel<<<small_blocks, threads>>>(Bp);
    normalize_kernel<<<big_blocks, threads>>>(feat, bidx, w, bias, out, N);
}